// round 5
// baseline (speedup 1.0000x reference)
#include <cuda_runtime.h>
#include <math.h>

#define NB     32
#define NA     33600
#define K_TOP  1000
#define NBINS  2048    // coarse bins: score_bits >> 19 (scores in (0,1) -> bin <= 2031)
#define NSUB   2048    // refine bins: bits[18:8] (only if coarse bin overflows NCAND)
#define NCAND  2048
#define NA4    (NA / 4)   // 8400

// scratch (static device globals — no allocation)
__device__ float g_scores[NB * NA];   // 4.3 MB, L2-resident
__device__ int   g_keep[NB * K_TOP];

// Bitwise match of XLA GPU logistic: 1/(1+exp(-x)) with libdevice expf and
// IEEE div.rn (nvcc defaults, no fast-math). DO NOT refactor algebraically —
// output ordering must be bit-exact vs reference (rel_err 5e-9 confirms).
__device__ __forceinline__ float sigref(float x) {
    return 1.0f / (1.0f + expf(-x));
}

// ---------------------------------------------------------------------------
// Kernel 1: score[b,a] = sigmoid(cls)*sigmoid(obj), float4-vectorized.
// (measured 6.0us)
// ---------------------------------------------------------------------------
__global__ void score_kernel(const float* __restrict__ cls0, const float* __restrict__ cls1,
                             const float* __restrict__ cls2,
                             const float* __restrict__ obj0, const float* __restrict__ obj1,
                             const float* __restrict__ obj2) {
    int i4 = blockIdx.x * blockDim.x + threadIdx.x;
    if (i4 >= NB * NA4) return;
    int b  = i4 / NA4;
    int a4 = i4 - b * NA4;
    const float4 *cp, *op;
    int p4;
    if (a4 < 6400)      { cp = (const float4*)cls0 + b * 6400; op = (const float4*)obj0 + b * 6400; p4 = a4; }
    else if (a4 < 8000) { cp = (const float4*)cls1 + b * 1600; op = (const float4*)obj1 + b * 1600; p4 = a4 - 6400; }
    else                { cp = (const float4*)cls2 + b * 400;  op = (const float4*)obj2 + b * 400;  p4 = a4 - 8000; }
    float4 c = cp[p4];
    float4 o = op[p4];
    float4 r;
    r.x = sigref(c.x) * sigref(o.x);
    r.y = sigref(c.y) * sigref(o.y);
    r.z = sigref(c.z) * sigref(o.z);
    r.w = sigref(c.w) * sigref(o.w);
    ((float4*)g_scores)[i4] = r;
}

// ---------------------------------------------------------------------------
// Kernel 2: exact sorted top-1000 per batch (one CTA per batch, 1024 threads)
// ---------------------------------------------------------------------------

// Warp-aggregated histogram add: lanes with equal bins elect a leader that
// adds popc once. Kills the 32-cyc/warp single-bank ATOMS serialization on
// the hot bins. 'bin' must be a sentinel (>= nbins distinct value) for
// inactive lanes; full-mask collectives (loop is uniform).
__device__ __forceinline__ void hist_add(unsigned int* hist, unsigned int bin, bool valid) {
    unsigned int key = valid ? bin : 0xFFFFFFFFu;
    unsigned int mask = __match_any_sync(0xFFFFFFFFu, key);
    if (valid) {
        int lane = threadIdx.x & 31;
        int leader = __ffs(mask) - 1;
        if (lane == leader) atomicAdd(&hist[bin], __popc(mask));
    }
}

// Find threshold bin (descending): largest bin T with
// count(bins > T) < K <= count(bins >= T). nbins = 2048 (per = 2).
__device__ void find_thresh(const unsigned int* hist, int nbins, int K, int tid,
                            int* wsum, int* s_bin, int* s_above) {
    int per  = nbins >> 10;
    int base = nbins - 1 - tid * per;
    int tsum = 0;
    for (int q = 0; q < per; q++) tsum += (int)hist[base - q];

    int lane = tid & 31, wid = tid >> 5;
    int x = tsum;
#pragma unroll
    for (int d = 1; d < 32; d <<= 1) {
        int n = __shfl_up_sync(0xffffffffu, x, d);
        if (lane >= d) x += n;
    }
    if (lane == 31) wsum[wid] = x;
    __syncthreads();
    if (wid == 0) {
        int w = wsum[lane];
#pragma unroll
        for (int d = 1; d < 32; d <<= 1) {
            int n = __shfl_up_sync(0xffffffffu, w, d);
            if (lane >= d) w += n;
        }
        wsum[lane] = w;
    }
    __syncthreads();
    int excl = (wid == 0 ? 0 : wsum[wid - 1]) + (x - tsum);

    if (excl < K && excl + tsum >= K) {     // exactly one thread
        int c = excl;
        for (int q = 0; q < per; q++) {
            int bin = base - q;
            int h = (int)hist[bin];
            if (c + h >= K) { *s_bin = bin; *s_above = c; break; }
            c += h;
        }
    }
    __syncthreads();
}

// Register compare-exchange with warp shuffle partner (j <= 16).
__device__ __forceinline__ unsigned long long cmpex_shfl(unsigned long long v, int i,
                                                         unsigned int j, unsigned int k) {
    unsigned long long o = __shfl_xor_sync(0xFFFFFFFFu, v, j);
    bool lower = ((i & j) == 0);
    bool desc  = ((i & (int)k) == 0);
    bool take_max = (desc == lower);
    return take_max ? (v > o ? v : o) : (v < o ? v : o);
}

__global__ __launch_bounds__(1024) void topk_kernel(float* __restrict__ dout) {
    __shared__ unsigned int       hist[NBINS];    // 8 KB
    __shared__ unsigned long long cand[NCAND];    // 16 KB
    __shared__ int  wsum[32];
    __shared__ int  s_bin, s_above;
    __shared__ unsigned int s_cnt;

    int b = blockIdx.x;
    int tid = threadIdx.x;
    int lane = tid & 31;
    const uint4* sv = (const uint4*)(g_scores + b * NA);

    // Phase 1: coarse histogram on bits >> 19, warp-aggregated atomics.
    for (int q = tid; q < NBINS; q += 1024) hist[q] = 0u;
    __syncthreads();
    for (int base = 0; base < NA4; base += 1024) {
        int q = base + tid;
        bool valid = q < NA4;
        uint4 v = valid ? sv[q] : make_uint4(0u, 0u, 0u, 0u);
        hist_add(hist, v.x >> 19, valid);
        hist_add(hist, v.y >> 19, valid);
        hist_add(hist, v.z >> 19, valid);
        hist_add(hist, v.w >> 19, valid);
    }
    __syncthreads();
    find_thresh(hist, NBINS, K_TOP, tid, wsum, &s_bin, &s_above);
    int T = s_bin;
    int need2 = K_TOP - s_above;
    int binT_count = (int)hist[T];
    __syncthreads();

    unsigned int cut;
    if (s_above + binT_count <= NCAND) {
        cut = (unsigned int)T << 19;            // common case
    } else {
        // Rare: refine bin T on bits[18:8].
        for (int q = tid; q < NSUB; q += 1024) hist[q] = 0u;
        __syncthreads();
        for (int base = 0; base < NA4; base += 1024) {
            int q = base + tid;
            bool valid = q < NA4;
            uint4 v = valid ? sv[q] : make_uint4(0u, 0u, 0u, 0u);
            hist_add(hist, (v.x >> 8) & 2047u, valid && (int)(v.x >> 19) == T);
            hist_add(hist, (v.y >> 8) & 2047u, valid && (int)(v.y >> 19) == T);
            hist_add(hist, (v.z >> 8) & 2047u, valid && (int)(v.z >> 19) == T);
            hist_add(hist, (v.w >> 8) & 2047u, valid && (int)(v.w >> 19) == T);
        }
        __syncthreads();
        find_thresh(hist, NSUB, need2, tid, wsum, &s_bin, &s_above);
        cut = ((unsigned int)T << 19) | ((unsigned int)s_bin << 8);
        __syncthreads();
    }

    // Phase 2: warp-aggregated compaction of candidates (bits >= cut).
    // key = (bits << 32) | ~index : bigger key == better (score desc, idx asc).
    if (tid == 0) s_cnt = 0u;
    __syncthreads();
    for (int base = 0; base < NA4; base += 1024) {
        int q = base + tid;
        bool valid = q < NA4;
        uint4 v = valid ? sv[q] : make_uint4(0u, 0u, 0u, 0u);
        int a0 = q * 4;
#pragma unroll
        for (int e = 0; e < 4; e++) {
            unsigned int bits = (e == 0) ? v.x : (e == 1) ? v.y : (e == 2) ? v.z : v.w;
            bool keep = valid && bits >= cut;
            unsigned int m = __ballot_sync(0xFFFFFFFFu, keep);
            if (m) {
                int leader = __ffs(m) - 1;
                unsigned int bpos = 0;
                if (lane == leader) bpos = atomicAdd(&s_cnt, (unsigned int)__popc(m));
                bpos = __shfl_sync(0xFFFFFFFFu, bpos, leader);
                if (keep) {
                    unsigned int pos = bpos + (unsigned int)__popc(m & ((1u << lane) - 1u));
                    if (pos < NCAND)
                        cand[pos] = ((unsigned long long)bits << 32) |
                                    (unsigned long long)(0xFFFFFFFFu - (unsigned int)(a0 + e));
                }
            }
        }
    }
    __syncthreads();
    int cnt = (int)s_cnt; if (cnt > NCAND) cnt = NCAND;
    for (int q = cnt + tid; q < NCAND; q += 1024) cand[q] = 0ull;
    __syncthreads();

    // Phase 3: hybrid bitonic sort of 2048 keys, descending.
    // Thread owns elements i0 = tid and i1 = tid + 1024. All stages with
    // j <= 16 run in registers via shuffle (partner lane = lane ^ j).
    {
        int i0 = tid, i1 = tid + 1024;
        unsigned long long v0 = cand[i0], v1 = cand[i1];
        // k = 2..32 entirely in registers (15 stages, 0 barriers)
#pragma unroll
        for (unsigned int k = 2; k <= 32; k <<= 1) {
            for (unsigned int j = k >> 1; j >= 1; j >>= 1) {
                v0 = cmpex_shfl(v0, i0, j, k);
                v1 = cmpex_shfl(v1, i1, j, k);
            }
        }
        cand[i0] = v0; cand[i1] = v1;
        __syncthreads();

        for (unsigned int k = 64; k <= NCAND; k <<= 1) {
            // smem stages: j = k/2 .. 32
            for (unsigned int j = k >> 1; j >= 32; j >>= 1) {
#pragma unroll
                for (int s = 0; s < 2; s++) {
                    int i = tid + s * 1024;
                    int ixj = i ^ (int)j;
                    if (ixj > i) {
                        unsigned long long A = cand[i], B = cand[ixj];
                        bool desc = ((i & (int)k) == 0);
                        if (desc ? (A < B) : (A > B)) { cand[i] = B; cand[ixj] = A; }
                    }
                }
                __syncthreads();
            }
            // register stages: j = 16 .. 1
            v0 = cand[i0]; v1 = cand[i1];
            for (unsigned int j = 16; j >= 1; j >>= 1) {
                v0 = cmpex_shfl(v0, i0, j, k);
                v1 = cmpex_shfl(v1, i1, j, k);
            }
            cand[i0] = v0; cand[i1] = v1;
            __syncthreads();
        }
    }

    // Phase 4: emit kept indices + score column of dets
    if (tid < K_TOP) {
        unsigned long long key = cand[tid];
        unsigned int bits = (unsigned int)(key >> 32);
        unsigned int a    = 0xFFFFFFFFu - (unsigned int)(key & 0xFFFFFFFFull);
        g_keep[b * K_TOP + tid] = (int)a;
        dout[b * (K_TOP * 5) + tid * 5 + 4] = __uint_as_float(bits);
    }
}

// ---------------------------------------------------------------------------
// Kernel 3: decode kept anchors. Channel-major tasking (det fast index).
// ---------------------------------------------------------------------------
#define NDET (NB * K_TOP)

__global__ void decode_kernel(const float* __restrict__ bbox0, const float* __restrict__ bbox1,
                              const float* __restrict__ bbox2,
                              const float* __restrict__ kpt0,  const float* __restrict__ kpt1,
                              const float* __restrict__ kpt2,
                              const float* __restrict__ vis0,  const float* __restrict__ vis1,
                              const float* __restrict__ vis2,
                              float* __restrict__ dout) {
    const int NTASK = NDET * 18;
    int task = blockIdx.x * blockDim.x + threadIdx.x;
    if (task >= NTASK) return;
    int det = task % NDET;
    int sub = task / NDET;
    int b   = det / K_TOP;
    int a   = g_keep[det];

    int p, HW, l;
    float s, px, py;
    if (a < 25600)      { p = a;         HW = 25600; s = 8.0f;  l = 0; px = (float)(p % 160) * 8.0f;  py = (float)(p / 160) * 8.0f;  }
    else if (a < 32000) { p = a - 25600; HW = 6400;  s = 16.0f; l = 1; px = (float)(p % 80)  * 16.0f; py = (float)(p / 80)  * 16.0f; }
    else                { p = a - 32000; HW = 1600;  s = 32.0f; l = 2; px = (float)(p % 40)  * 32.0f; py = (float)(p / 40)  * 32.0f; }

    if (sub < 17) {
        int k = sub;
        const float* kp = (l == 0) ? kpt0 : (l == 1) ? kpt1 : kpt2;
        const float* vp = (l == 0) ? vis0 : (l == 1) ? vis1 : vis2;
        float kx = kp[(b * 34 + 2 * k)     * HW + p];
        float ky = kp[(b * 34 + 2 * k + 1) * HW + p];
        float v  = vp[(b * 17 + k)         * HW + p];
        int off = NDET * 5 + det * 51 + k * 3;
        dout[off + 0] = kx * s + px;
        dout[off + 1] = ky * s + py;
        dout[off + 2] = sigref(v);
    } else {
        const float* bp = (l == 0) ? bbox0 : (l == 1) ? bbox1 : bbox2;
        float bx = bp[(b * 4 + 0) * HW + p];
        float by = bp[(b * 4 + 1) * HW + p];
        float bw = bp[(b * 4 + 2) * HW + p];
        float bh = bp[(b * 4 + 3) * HW + p];
        float x  = bx * s + px;
        float y  = by * s + py;
        float hw = expf(bw) * s * 0.5f;
        float hh = expf(bh) * s * 0.5f;
        int off = det * 5;
        dout[off + 0] = x - hw;
        dout[off + 1] = y - hh;
        dout[off + 2] = x + hw;
        dout[off + 3] = y + hh;
    }
}

// ---------------------------------------------------------------------------
extern "C" void kernel_launch(void* const* d_in, const int* in_sizes, int n_in,
                              void* d_out, int out_size) {
    const float* cls0  = (const float*)d_in[0];
    const float* cls1  = (const float*)d_in[1];
    const float* cls2  = (const float*)d_in[2];
    const float* bbox0 = (const float*)d_in[3];
    const float* bbox1 = (const float*)d_in[4];
    const float* bbox2 = (const float*)d_in[5];
    const float* obj0  = (const float*)d_in[6];
    const float* obj1  = (const float*)d_in[7];
    const float* obj2  = (const float*)d_in[8];
    const float* kpt0  = (const float*)d_in[9];
    const float* kpt1  = (const float*)d_in[10];
    const float* kpt2  = (const float*)d_in[11];
    const float* vis0  = (const float*)d_in[12];
    const float* vis1  = (const float*)d_in[13];
    const float* vis2  = (const float*)d_in[14];
    float* dout = (float*)d_out;

    score_kernel<<<(NB * NA4 + 255) / 256, 256>>>(cls0, cls1, cls2, obj0, obj1, obj2);
    topk_kernel<<<NB, 1024>>>(dout);
    decode_kernel<<<(NDET * 18 + 255) / 256, 256>>>(bbox0, bbox1, bbox2,
                                                    kpt0, kpt1, kpt2,
                                                    vis0, vis1, vis2, dout);
}

// round 6
// speedup vs baseline: 1.3369x; 1.3369x over previous
#include <cuda_runtime.h>
#include <math.h>

#define NB     32
#define NA     33600
#define K_TOP  1000
#define NBINS  2048      // coarse bins: score_bits >> 19
#define NSUB   2048      // refine bins: bits[18:8] (only if coarse bin overflows NCAND)
#define NCAND  2048
#define NA4    (NA / 4)  // 8400
#define NIT    9         // ceil(NA4 / 1024) register-cache iterations
#define HCOPY  8
#define HSTRIDE 2052     // 2052 % 32 == 4 -> copies 0..7 on distinct banks (4c mod 32)

// dynamic smem layout (bytes)
#define SM_H8_B    (HCOPY * HSTRIDE * 4)          // 65664
#define SM_HIST_B  (NBINS * 4)                    // 8192
#define SM_CAND_B  (NCAND * 8)                    // 16384
#define SM_TOTAL_B (SM_H8_B + SM_HIST_B + SM_CAND_B)  // 90240

// scratch (static device globals — no allocation)
__device__ float g_scores[NB * NA];   // 4.3 MB, L2-resident
__device__ int   g_keep[NB * K_TOP];

// Bitwise match of XLA GPU logistic: 1/(1+exp(-x)) with libdevice expf and
// IEEE div.rn (nvcc defaults, no fast-math). DO NOT refactor algebraically —
// output ordering must be bit-exact vs reference (rel_err 5e-9 confirms).
__device__ __forceinline__ float sigref(float x) {
    return 1.0f / (1.0f + expf(-x));
}

// ---------------------------------------------------------------------------
// Kernel 1: score[b,a] = sigmoid(cls)*sigmoid(obj), float4-vectorized.
// (measured 6.0us — unchanged from R4)
// ---------------------------------------------------------------------------
__global__ void score_kernel(const float* __restrict__ cls0, const float* __restrict__ cls1,
                             const float* __restrict__ cls2,
                             const float* __restrict__ obj0, const float* __restrict__ obj1,
                             const float* __restrict__ obj2) {
    int i4 = blockIdx.x * blockDim.x + threadIdx.x;
    if (i4 >= NB * NA4) return;
    int b  = i4 / NA4;
    int a4 = i4 - b * NA4;
    const float4 *cp, *op;
    int p4;
    if (a4 < 6400)      { cp = (const float4*)cls0 + b * 6400; op = (const float4*)obj0 + b * 6400; p4 = a4; }
    else if (a4 < 8000) { cp = (const float4*)cls1 + b * 1600; op = (const float4*)obj1 + b * 1600; p4 = a4 - 6400; }
    else                { cp = (const float4*)cls2 + b * 400;  op = (const float4*)obj2 + b * 400;  p4 = a4 - 8000; }
    float4 c = cp[p4];
    float4 o = op[p4];
    float4 r;
    r.x = sigref(c.x) * sigref(o.x);
    r.y = sigref(c.y) * sigref(o.y);
    r.z = sigref(c.z) * sigref(o.z);
    r.w = sigref(c.w) * sigref(o.w);
    ((float4*)g_scores)[i4] = r;
}

// ---------------------------------------------------------------------------
// Kernel 2: exact sorted top-1000 per batch (one CTA per batch, 1024 threads)
// ---------------------------------------------------------------------------

// Find threshold bin (descending): largest bin T with
// count(bins > T) < K <= count(bins >= T). nbins = 2048 (per = 2).
__device__ void find_thresh(const unsigned int* hist, int nbins, int K, int tid,
                            int* wsum, int* s_bin, int* s_above) {
    int per  = nbins >> 10;
    int base = nbins - 1 - tid * per;
    int tsum = 0;
    for (int q = 0; q < per; q++) tsum += (int)hist[base - q];

    int lane = tid & 31, wid = tid >> 5;
    int x = tsum;
#pragma unroll
    for (int d = 1; d < 32; d <<= 1) {
        int n = __shfl_up_sync(0xffffffffu, x, d);
        if (lane >= d) x += n;
    }
    if (lane == 31) wsum[wid] = x;
    __syncthreads();
    if (wid == 0) {
        int w = wsum[lane];
#pragma unroll
        for (int d = 1; d < 32; d <<= 1) {
            int n = __shfl_up_sync(0xffffffffu, w, d);
            if (lane >= d) w += n;
        }
        wsum[lane] = w;
    }
    __syncthreads();
    int excl = (wid == 0 ? 0 : wsum[wid - 1]) + (x - tsum);

    if (excl < K && excl + tsum >= K) {     // exactly one thread
        int c = excl;
        for (int q = 0; q < per; q++) {
            int bin = base - q;
            int h = (int)hist[bin];
            if (c + h >= K) { *s_bin = bin; *s_above = c; break; }
            c += h;
        }
    }
    __syncthreads();
}

extern __shared__ unsigned char sm_raw[];

__global__ __launch_bounds__(1024) void topk_kernel(float* __restrict__ dout) {
    unsigned int*       hist8 = (unsigned int*)sm_raw;                        // 8 x 2052
    unsigned int*       hist  = (unsigned int*)(sm_raw + SM_H8_B);            // 2048
    unsigned long long* cand  = (unsigned long long*)(sm_raw + SM_H8_B + SM_HIST_B); // 2048
    __shared__ int  wsum[32];
    __shared__ int  s_bin, s_above;
    __shared__ unsigned int s_cnt;

    int b = blockIdx.x;
    int tid = threadIdx.x;
    int lane = tid & 31;
    const uint4* sv = (const uint4*)(g_scores + b * NA);

    // Load this thread's 9 uint4 chunks into registers (single L2 read pass).
    // Out-of-range -> zero bits (bin 0; never reaches the top-K cut).
    uint4 vloc[NIT];
#pragma unroll
    for (int it = 0; it < NIT; it++) {
        int q = it * 1024 + tid;
        vloc[it] = (q < NA4) ? sv[q] : make_uint4(0u, 0u, 0u, 0u);
    }

    // Phase 1: coarse histogram on bits >> 19. 8 lane-spread copies with a
    // bank-skewed stride: same-bin lanes within a warp land on 8 distinct
    // banks -> within-warp atomic conflict degree /8 at zero instr overhead.
    for (int q = tid; q < HCOPY * HSTRIDE; q += 1024) hist8[q] = 0u;
    __syncthreads();
    {
        unsigned int* hp = hist8 + (lane & 7) * HSTRIDE;
#pragma unroll
        for (int it = 0; it < NIT; it++) {
            uint4 v = vloc[it];
            atomicAdd(&hp[v.x >> 19], 1u);
            atomicAdd(&hp[v.y >> 19], 1u);
            atomicAdd(&hp[v.z >> 19], 1u);
            atomicAdd(&hp[v.w >> 19], 1u);
        }
    }
    __syncthreads();
    for (int q = tid; q < NBINS; q += 1024) {
        unsigned int s = 0;
#pragma unroll
        for (int c = 0; c < HCOPY; c++) s += hist8[c * HSTRIDE + q];
        hist[q] = s;
    }
    __syncthreads();
    find_thresh(hist, NBINS, K_TOP, tid, wsum, &s_bin, &s_above);
    int T = s_bin;
    int need2 = K_TOP - s_above;
    int binT_count = (int)hist[T];
    __syncthreads();

    unsigned int cut;
    if (s_above + binT_count <= NCAND) {
        cut = (unsigned int)T << 19;            // common case: no refine
    } else {
        // Rare: refine bin T on bits[18:8] (few members -> plain atomics fine).
        for (int q = tid; q < NSUB; q += 1024) hist[q] = 0u;
        __syncthreads();
#pragma unroll
        for (int it = 0; it < NIT; it++) {
            uint4 v = vloc[it];
            if ((int)(v.x >> 19) == T) atomicAdd(&hist[(v.x >> 8) & 2047u], 1u);
            if ((int)(v.y >> 19) == T) atomicAdd(&hist[(v.y >> 8) & 2047u], 1u);
            if ((int)(v.z >> 19) == T) atomicAdd(&hist[(v.z >> 8) & 2047u], 1u);
            if ((int)(v.w >> 19) == T) atomicAdd(&hist[(v.w >> 8) & 2047u], 1u);
        }
        __syncthreads();
        find_thresh(hist, NSUB, need2, tid, wsum, &s_bin, &s_above);
        cut = ((unsigned int)T << 19) | ((unsigned int)s_bin << 8);
        __syncthreads();
    }

    // Phase 2: compact candidates (bits >= cut) from the register cache.
    // key = (bits << 32) | ~index : bigger key == better (score desc, idx asc).
    if (tid == 0) s_cnt = 0u;
    __syncthreads();
#pragma unroll
    for (int it = 0; it < NIT; it++) {
        uint4 v = vloc[it];
        int a0 = (it * 1024 + tid) * 4;
#pragma unroll
        for (int e = 0; e < 4; e++) {
            unsigned int bits = (e == 0) ? v.x : (e == 1) ? v.y : (e == 2) ? v.z : v.w;
            if (bits >= cut) {
                unsigned int pos = atomicAdd(&s_cnt, 1u);
                if (pos < NCAND)
                    cand[pos] = ((unsigned long long)bits << 32) |
                                (unsigned long long)(0xFFFFFFFFu - (unsigned int)(a0 + e));
            }
        }
    }
    __syncthreads();
    int cnt = (int)s_cnt; if (cnt > NCAND) cnt = NCAND;
    int sortn = (cnt <= 1024) ? 1024 : 2048;   // uniform across block (from smem)
    for (int q = cnt + tid; q < sortn; q += 1024) cand[q] = 0ull;
    __syncthreads();

    // Phase 3: bitonic sort of sortn keys, descending (R4's known-good form;
    // 55 barriers when sortn==1024, 66 when 2048).
    for (unsigned int k = 2; k <= (unsigned int)sortn; k <<= 1) {
        for (unsigned int j = k >> 1; j > 0; j >>= 1) {
            for (int i = tid; i < sortn; i += 1024) {
                int ixj = i ^ (int)j;
                if (ixj > i) {
                    unsigned long long A = cand[i], B = cand[ixj];
                    bool desc = ((i & (int)k) == 0);
                    if (desc ? (A < B) : (A > B)) { cand[i] = B; cand[ixj] = A; }
                }
            }
            __syncthreads();
        }
    }

    // Phase 4: emit kept indices + score column of dets
    if (tid < K_TOP) {
        unsigned long long key = cand[tid];
        unsigned int bits = (unsigned int)(key >> 32);
        unsigned int a    = 0xFFFFFFFFu - (unsigned int)(key & 0xFFFFFFFFull);
        g_keep[b * K_TOP + tid] = (int)a;
        dout[b * (K_TOP * 5) + tid * 5 + 4] = __uint_as_float(bits);
    }
}

// ---------------------------------------------------------------------------
// Kernel 3: decode kept anchors. Channel-major tasking (det fast index).
// (unchanged from R4)
// ---------------------------------------------------------------------------
#define NDET (NB * K_TOP)

__global__ void decode_kernel(const float* __restrict__ bbox0, const float* __restrict__ bbox1,
                              const float* __restrict__ bbox2,
                              const float* __restrict__ kpt0,  const float* __restrict__ kpt1,
                              const float* __restrict__ kpt2,
                              const float* __restrict__ vis0,  const float* __restrict__ vis1,
                              const float* __restrict__ vis2,
                              float* __restrict__ dout) {
    const int NTASK = NDET * 18;
    int task = blockIdx.x * blockDim.x + threadIdx.x;
    if (task >= NTASK) return;
    int det = task % NDET;
    int sub = task / NDET;
    int b   = det / K_TOP;
    int a   = g_keep[det];

    int p, HW, l;
    float s, px, py;
    if (a < 25600)      { p = a;         HW = 25600; s = 8.0f;  l = 0; px = (float)(p % 160) * 8.0f;  py = (float)(p / 160) * 8.0f;  }
    else if (a < 32000) { p = a - 25600; HW = 6400;  s = 16.0f; l = 1; px = (float)(p % 80)  * 16.0f; py = (float)(p / 80)  * 16.0f; }
    else                { p = a - 32000; HW = 1600;  s = 32.0f; l = 2; px = (float)(p % 40)  * 32.0f; py = (float)(p / 40)  * 32.0f; }

    if (sub < 17) {
        int k = sub;
        const float* kp = (l == 0) ? kpt0 : (l == 1) ? kpt1 : kpt2;
        const float* vp = (l == 0) ? vis0 : (l == 1) ? vis1 : vis2;
        float kx = kp[(b * 34 + 2 * k)     * HW + p];
        float ky = kp[(b * 34 + 2 * k + 1) * HW + p];
        float v  = vp[(b * 17 + k)         * HW + p];
        int off = NDET * 5 + det * 51 + k * 3;
        dout[off + 0] = kx * s + px;
        dout[off + 1] = ky * s + py;
        dout[off + 2] = sigref(v);
    } else {
        const float* bp = (l == 0) ? bbox0 : (l == 1) ? bbox1 : bbox2;
        float bx = bp[(b * 4 + 0) * HW + p];
        float by = bp[(b * 4 + 1) * HW + p];
        float bw = bp[(b * 4 + 2) * HW + p];
        float bh = bp[(b * 4 + 3) * HW + p];
        float x  = bx * s + px;
        float y  = by * s + py;
        float hw = expf(bw) * s * 0.5f;
        float hh = expf(bh) * s * 0.5f;
        int off = det * 5;
        dout[off + 0] = x - hw;
        dout[off + 1] = y - hh;
        dout[off + 2] = x + hw;
        dout[off + 3] = y + hh;
    }
}

// ---------------------------------------------------------------------------
extern "C" void kernel_launch(void* const* d_in, const int* in_sizes, int n_in,
                              void* d_out, int out_size) {
    const float* cls0  = (const float*)d_in[0];
    const float* cls1  = (const float*)d_in[1];
    const float* cls2  = (const float*)d_in[2];
    const float* bbox0 = (const float*)d_in[3];
    const float* bbox1 = (const float*)d_in[4];
    const float* bbox2 = (const float*)d_in[5];
    const float* obj0  = (const float*)d_in[6];
    const float* obj1  = (const float*)d_in[7];
    const float* obj2  = (const float*)d_in[8];
    const float* kpt0  = (const float*)d_in[9];
    const float* kpt1  = (const float*)d_in[10];
    const float* kpt2  = (const float*)d_in[11];
    const float* vis0  = (const float*)d_in[12];
    const float* vis1  = (const float*)d_in[13];
    const float* vis2  = (const float*)d_in[14];
    float* dout = (float*)d_out;

    cudaFuncSetAttribute(topk_kernel, cudaFuncAttributeMaxDynamicSharedMemorySize,
                         SM_TOTAL_B);

    score_kernel<<<(NB * NA4 + 255) / 256, 256>>>(cls0, cls1, cls2, obj0, obj1, obj2);
    topk_kernel<<<NB, 1024, SM_TOTAL_B>>>(dout);
    decode_kernel<<<(NDET * 18 + 255) / 256, 256>>>(bbox0, bbox1, bbox2,
                                                    kpt0, kpt1, kpt2,
                                                    vis0, vis1, vis2, dout);
}

// round 7
// speedup vs baseline: 1.3861x; 1.0368x over previous
#include <cuda_runtime.h>
#include <math.h>

#define NB     32
#define NA     33600
#define K_TOP  1000
#define NBINS  2048      // coarse bins: score_bits >> 19
#define NSUB   2048      // refine bins: bits[18:8]
#define NCAND  2048
#define NA4    (NA / 4)  // 8400
#define NIT    9         // ceil(NA4 / 1024) register-cache iterations
#define NDET   (NB * K_TOP)

// scratch (static device globals — no allocation)
__device__ float g_scores[NB * NA];   // 4.3 MB, L2-resident
__device__ int   g_keep[NDET];        // anchor per (batch, rank)
__device__ int   g_ord[NDET];         // per batch: (anchor<<10 | rank), anchor-ascending

// Bitwise match of XLA GPU logistic: 1/(1+exp(-x)) with libdevice expf and
// IEEE div.rn (nvcc defaults, no fast-math). DO NOT refactor algebraically —
// output ordering must be bit-exact vs reference (rel_err 5e-9 confirms).
__device__ __forceinline__ float sigref(float x) {
    return 1.0f / (1.0f + expf(-x));
}

// ---------------------------------------------------------------------------
// Kernel 1: score[b,a] = sigmoid(cls)*sigmoid(obj), float4-vectorized.
// (measured ~6.0-6.4us — unchanged)
// ---------------------------------------------------------------------------
__global__ void score_kernel(const float* __restrict__ cls0, const float* __restrict__ cls1,
                             const float* __restrict__ cls2,
                             const float* __restrict__ obj0, const float* __restrict__ obj1,
                             const float* __restrict__ obj2) {
    int i4 = blockIdx.x * blockDim.x + threadIdx.x;
    if (i4 >= NB * NA4) return;
    int b  = i4 / NA4;
    int a4 = i4 - b * NA4;
    const float4 *cp, *op;
    int p4;
    if (a4 < 6400)      { cp = (const float4*)cls0 + b * 6400; op = (const float4*)obj0 + b * 6400; p4 = a4; }
    else if (a4 < 8000) { cp = (const float4*)cls1 + b * 1600; op = (const float4*)obj1 + b * 1600; p4 = a4 - 6400; }
    else                { cp = (const float4*)cls2 + b * 400;  op = (const float4*)obj2 + b * 400;  p4 = a4 - 8000; }
    float4 c = cp[p4];
    float4 o = op[p4];
    float4 r;
    r.x = sigref(c.x) * sigref(o.x);
    r.y = sigref(c.y) * sigref(o.y);
    r.z = sigref(c.z) * sigref(o.z);
    r.w = sigref(c.w) * sigref(o.w);
    ((float4*)g_scores)[i4] = r;
}

// ---------------------------------------------------------------------------
// Kernel 2: exact sorted top-1000 per batch (one CTA per batch, 1024 threads)
// ---------------------------------------------------------------------------

// Find threshold bin (descending): largest bin T with
// count(bins > T) < K <= count(bins >= T). nbins = 2048 (per = 2).
__device__ void find_thresh(const unsigned int* hist, int nbins, int K, int tid,
                            int* wsum, int* s_bin, int* s_above) {
    int per  = nbins >> 10;
    int base = nbins - 1 - tid * per;
    int tsum = 0;
    for (int q = 0; q < per; q++) tsum += (int)hist[base - q];

    int lane = tid & 31, wid = tid >> 5;
    int x = tsum;
#pragma unroll
    for (int d = 1; d < 32; d <<= 1) {
        int n = __shfl_up_sync(0xffffffffu, x, d);
        if (lane >= d) x += n;
    }
    if (lane == 31) wsum[wid] = x;
    __syncthreads();
    if (wid == 0) {
        int w = wsum[lane];
#pragma unroll
        for (int d = 1; d < 32; d <<= 1) {
            int n = __shfl_up_sync(0xffffffffu, w, d);
            if (lane >= d) w += n;
        }
        wsum[lane] = w;
    }
    __syncthreads();
    int excl = (wid == 0 ? 0 : wsum[wid - 1]) + (x - tsum);

    if (excl < K && excl + tsum >= K) {     // exactly one thread
        int c = excl;
        for (int q = 0; q < per; q++) {
            int bin = base - q;
            int h = (int)hist[bin];
            if (c + h >= K) { *s_bin = bin; *s_above = c; break; }
            c += h;
        }
    }
    __syncthreads();
}

__global__ __launch_bounds__(1024) void topk_kernel(float* __restrict__ dout) {
    __shared__ unsigned int       hist[NBINS];    // 8 KB
    __shared__ unsigned long long cand[NCAND];    // 16 KB (reused as u32 for ord sort)
    __shared__ int  wsum[32];
    __shared__ int  s_bin, s_above;
    __shared__ unsigned int s_cnt;

    int b = blockIdx.x;
    int tid = threadIdx.x;
    const uint4* sv = (const uint4*)(g_scores + b * NA);

    // Register-cache this thread's 9 uint4 chunks (single L2 read pass).
    uint4 vloc[NIT];
#pragma unroll
    for (int it = 0; it < NIT; it++) {
        int q = it * 1024 + tid;
        vloc[it] = (q < NA4) ? sv[q] : make_uint4(0u, 0u, 0u, 0u);
    }

    // Phase 1: coarse histogram on bits >> 19 (plain atomics — R4 baseline).
    for (int q = tid; q < NBINS; q += 1024) hist[q] = 0u;
    __syncthreads();
#pragma unroll
    for (int it = 0; it < NIT; it++) {
        uint4 v = vloc[it];
        atomicAdd(&hist[v.x >> 19], 1u);
        atomicAdd(&hist[v.y >> 19], 1u);
        atomicAdd(&hist[v.z >> 19], 1u);
        atomicAdd(&hist[v.w >> 19], 1u);
    }
    __syncthreads();
    find_thresh(hist, NBINS, K_TOP, tid, wsum, &s_bin, &s_above);
    int T = s_bin;
    int need2 = K_TOP - s_above;
    int binT_count = (int)hist[T];
    __syncthreads();

    unsigned int cut;
    if (s_above + binT_count <= 1024) {
        // bin T fits a 1024-wide sort -> no refine needed.
        cut = (unsigned int)T << 19;
    } else {
        // Refine bin T on bits[18:8] so cnt lands in [1000, ~1010] (sort 1024).
        for (int q = tid; q < NSUB; q += 1024) hist[q] = 0u;
        __syncthreads();
#pragma unroll
        for (int it = 0; it < NIT; it++) {
            uint4 v = vloc[it];
            if ((int)(v.x >> 19) == T) atomicAdd(&hist[(v.x >> 8) & 2047u], 1u);
            if ((int)(v.y >> 19) == T) atomicAdd(&hist[(v.y >> 8) & 2047u], 1u);
            if ((int)(v.z >> 19) == T) atomicAdd(&hist[(v.z >> 8) & 2047u], 1u);
            if ((int)(v.w >> 19) == T) atomicAdd(&hist[(v.w >> 8) & 2047u], 1u);
        }
        __syncthreads();
        find_thresh(hist, NSUB, need2, tid, wsum, &s_bin, &s_above);
        cut = ((unsigned int)T << 19) | ((unsigned int)s_bin << 8);
        __syncthreads();
    }

    // Phase 2: compact candidates (bits >= cut) from the register cache.
    // key = (bits << 32) | ~index : bigger key == better (score desc, idx asc).
    if (tid == 0) s_cnt = 0u;
    __syncthreads();
#pragma unroll
    for (int it = 0; it < NIT; it++) {
        uint4 v = vloc[it];
        int a0 = (it * 1024 + tid) * 4;
#pragma unroll
        for (int e = 0; e < 4; e++) {
            unsigned int bits = (e == 0) ? v.x : (e == 1) ? v.y : (e == 2) ? v.z : v.w;
            if (bits >= cut) {
                unsigned int pos = atomicAdd(&s_cnt, 1u);
                if (pos < NCAND)
                    cand[pos] = ((unsigned long long)bits << 32) |
                                (unsigned long long)(0xFFFFFFFFu - (unsigned int)(a0 + e));
            }
        }
    }
    __syncthreads();
    int cnt = (int)s_cnt; if (cnt > NCAND) cnt = NCAND;
    int sortn = (cnt <= 1024) ? 1024 : 2048;   // uniform across block
    for (int q = cnt + tid; q < sortn; q += 1024) cand[q] = 0ull;
    __syncthreads();

    // Phase 3: bitonic sort of sortn keys, descending (55 passes when 1024).
    for (unsigned int k = 2; k <= (unsigned int)sortn; k <<= 1) {
        for (unsigned int j = k >> 1; j > 0; j >>= 1) {
            for (int i = tid; i < sortn; i += 1024) {
                int ixj = i ^ (int)j;
                if (ixj > i) {
                    unsigned long long A = cand[i], B = cand[ixj];
                    bool desc = ((i & (int)k) == 0);
                    if (desc ? (A < B) : (A > B)) { cand[i] = B; cand[ixj] = A; }
                }
            }
            __syncthreads();
        }
    }

    // Phase 4: emit kept indices + score column of dets
    unsigned int my_a = 0xFFFFFFFFu;
    if (tid < K_TOP) {
        unsigned long long key = cand[tid];
        unsigned int bits = (unsigned int)(key >> 32);
        my_a = 0xFFFFFFFFu - (unsigned int)(key & 0xFFFFFFFFull);
        g_keep[b * K_TOP + tid] = (int)my_a;
        dout[b * (K_TOP * 5) + tid * 5 + 4] = __uint_as_float(bits);
    }
    __syncthreads();

    // Phase 5: build anchor-ascending order for the decode gather.
    // key32 = anchor<<10 | rank (anchor<=33599 fits 16 bits; rank<1000 fits 10).
    // Pad to 1024 with 0xFFFFFFFF; ascending 32-bit bitonic (55 light passes).
    {
        unsigned int* ord = (unsigned int*)cand;
        ord[tid] = (tid < K_TOP) ? ((my_a << 10) | (unsigned int)tid) : 0xFFFFFFFFu;
        __syncthreads();
        for (unsigned int k = 2; k <= 1024; k <<= 1) {
            for (unsigned int j = k >> 1; j > 0; j >>= 1) {
                int i = tid;
                int ixj = i ^ (int)j;
                if (ixj > i) {
                    unsigned int A = ord[i], B = ord[ixj];
                    bool asc = ((i & (int)k) == 0);
                    if (asc ? (A > B) : (A < B)) { ord[i] = B; ord[ixj] = A; }
                }
                __syncthreads();
            }
        }
        if (tid < K_TOP) g_ord[b * K_TOP + tid] = (int)ord[tid];
    }
}

// ---------------------------------------------------------------------------
// Kernel 3: decode kept anchors in ANCHOR-SORTED order (sector sharing +
// DRAM row locality + level-uniform warps). Channel-major tasking, sorted
// position fastest. Output written at rank position (scattered, cheap).
// ---------------------------------------------------------------------------
__global__ void decode_kernel(const float* __restrict__ bbox0, const float* __restrict__ bbox1,
                              const float* __restrict__ bbox2,
                              const float* __restrict__ kpt0,  const float* __restrict__ kpt1,
                              const float* __restrict__ kpt2,
                              const float* __restrict__ vis0,  const float* __restrict__ vis1,
                              const float* __restrict__ vis2,
                              float* __restrict__ dout) {
    const int NTASK = NDET * 18;
    int task = blockIdx.x * blockDim.x + threadIdx.x;
    if (task >= NTASK) return;
    int j   = task % NDET;          // fast index: b*K_TOP + sorted_pos
    int sub = task / NDET;          // 0..16 = keypoint, 17 = bbox
    int b   = j / K_TOP;

    unsigned int key = (unsigned int)g_ord[j];
    int a    = (int)(key >> 10);
    int rank = (int)(key & 1023u);
    int det  = b * K_TOP + rank;

    int p, HW, l;
    float s, px, py;
    if (a < 25600)      { p = a;         HW = 25600; s = 8.0f;  l = 0; px = (float)(p % 160) * 8.0f;  py = (float)(p / 160) * 8.0f;  }
    else if (a < 32000) { p = a - 25600; HW = 6400;  s = 16.0f; l = 1; px = (float)(p % 80)  * 16.0f; py = (float)(p / 80)  * 16.0f; }
    else                { p = a - 32000; HW = 1600;  s = 32.0f; l = 2; px = (float)(p % 40)  * 32.0f; py = (float)(p / 40)  * 32.0f; }

    if (sub < 17) {
        int k = sub;
        const float* kp = (l == 0) ? kpt0 : (l == 1) ? kpt1 : kpt2;
        const float* vp = (l == 0) ? vis0 : (l == 1) ? vis1 : vis2;
        float kx = kp[(b * 34 + 2 * k)     * HW + p];
        float ky = kp[(b * 34 + 2 * k + 1) * HW + p];
        float v  = vp[(b * 17 + k)         * HW + p];
        int off = NDET * 5 + det * 51 + k * 3;
        dout[off + 0] = kx * s + px;
        dout[off + 1] = ky * s + py;
        dout[off + 2] = sigref(v);
    } else {
        const float* bp = (l == 0) ? bbox0 : (l == 1) ? bbox1 : bbox2;
        float bx = bp[(b * 4 + 0) * HW + p];
        float by = bp[(b * 4 + 1) * HW + p];
        float bw = bp[(b * 4 + 2) * HW + p];
        float bh = bp[(b * 4 + 3) * HW + p];
        float x  = bx * s + px;
        float y  = by * s + py;
        float hw = expf(bw) * s * 0.5f;
        float hh = expf(bh) * s * 0.5f;
        int off = det * 5;
        dout[off + 0] = x - hw;
        dout[off + 1] = y - hh;
        dout[off + 2] = x + hw;
        dout[off + 3] = y + hh;
    }
}

// ---------------------------------------------------------------------------
extern "C" void kernel_launch(void* const* d_in, const int* in_sizes, int n_in,
                              void* d_out, int out_size) {
    const float* cls0  = (const float*)d_in[0];
    const float* cls1  = (const float*)d_in[1];
    const float* cls2  = (const float*)d_in[2];
    const float* bbox0 = (const float*)d_in[3];
    const float* bbox1 = (const float*)d_in[4];
    const float* bbox2 = (const float*)d_in[5];
    const float* obj0  = (const float*)d_in[6];
    const float* obj1  = (const float*)d_in[7];
    const float* obj2  = (const float*)d_in[8];
    const float* kpt0  = (const float*)d_in[9];
    const float* kpt1  = (const float*)d_in[10];
    const float* kpt2  = (const float*)d_in[11];
    const float* vis0  = (const float*)d_in[12];
    const float* vis1  = (const float*)d_in[13];
    const float* vis2  = (const float*)d_in[14];
    float* dout = (float*)d_out;

    score_kernel<<<(NB * NA4 + 255) / 256, 256>>>(cls0, cls1, cls2, obj0, obj1, obj2);
    topk_kernel<<<NB, 1024>>>(dout);
    decode_kernel<<<(NDET * 18 + 255) / 256, 256>>>(bbox0, bbox1, bbox2,
                                                    kpt0, kpt1, kpt2,
                                                    vis0, vis1, vis2, dout);
}

// round 9
// speedup vs baseline: 1.5152x; 1.0931x over previous
#include <cuda_runtime.h>
#include <math.h>

#define NB     32
#define NA     33600
#define K_TOP  1000
#define NBINS  2048      // coarse bins: score_bits >> 19
#define NSUB   2048      // refine bins: bits[18:8]
#define NCAND  2048
#define NA4    (NA / 4)  // 8400
#define NIT    9         // ceil(NA4 / 1024) register-cache iterations
#define NDET   (NB * K_TOP)

// scratch (static device globals — no allocation)
__device__ float g_scores[NB * NA];   // 4.3 MB, L2-resident
__device__ int   g_keep[NDET];        // anchor per (batch, rank)

// Bitwise match of XLA GPU logistic: 1/(1+exp(-x)) with libdevice expf and
// IEEE div.rn (nvcc defaults, no fast-math). DO NOT refactor algebraically —
// output ordering must be bit-exact vs reference (rel_err 5e-9 confirms).
__device__ __forceinline__ float sigref(float x) {
    return 1.0f / (1.0f + expf(-x));
}

// ---------------------------------------------------------------------------
// Kernel 1: score[b,a] = sigmoid(cls)*sigmoid(obj), float4-vectorized.
// (measured ~6.2us — unchanged)
// ---------------------------------------------------------------------------
__global__ void score_kernel(const float* __restrict__ cls0, const float* __restrict__ cls1,
                             const float* __restrict__ cls2,
                             const float* __restrict__ obj0, const float* __restrict__ obj1,
                             const float* __restrict__ obj2) {
    int i4 = blockIdx.x * blockDim.x + threadIdx.x;
    if (i4 >= NB * NA4) return;
    int b  = i4 / NA4;
    int a4 = i4 - b * NA4;
    const float4 *cp, *op;
    int p4;
    if (a4 < 6400)      { cp = (const float4*)cls0 + b * 6400; op = (const float4*)obj0 + b * 6400; p4 = a4; }
    else if (a4 < 8000) { cp = (const float4*)cls1 + b * 1600; op = (const float4*)obj1 + b * 1600; p4 = a4 - 6400; }
    else                { cp = (const float4*)cls2 + b * 400;  op = (const float4*)obj2 + b * 400;  p4 = a4 - 8000; }
    float4 c = cp[p4];
    float4 o = op[p4];
    float4 r;
    r.x = sigref(c.x) * sigref(o.x);
    r.y = sigref(c.y) * sigref(o.y);
    r.z = sigref(c.z) * sigref(o.z);
    r.w = sigref(c.w) * sigref(o.w);
    ((float4*)g_scores)[i4] = r;
}

// ---------------------------------------------------------------------------
// Kernel 2: exact sorted top-1000 per batch (one CTA per batch, 1024 threads)
// Histogram-rank: no comparison sort at all (~7 barriers total).
// ---------------------------------------------------------------------------

// Find threshold bin (descending): largest bin T with
// count(bins > T) < K <= count(bins >= T). nbins = 2048 (per = 2).
__device__ void find_thresh(const unsigned int* hist, int nbins, int K, int tid,
                            int* wsum, int* s_bin, int* s_above) {
    int per  = nbins >> 10;
    int base = nbins - 1 - tid * per;
    int tsum = 0;
    for (int q = 0; q < per; q++) tsum += (int)hist[base - q];

    int lane = tid & 31, wid = tid >> 5;
    int x = tsum;
#pragma unroll
    for (int d = 1; d < 32; d <<= 1) {
        int n = __shfl_up_sync(0xffffffffu, x, d);
        if (lane >= d) x += n;
    }
    if (lane == 31) wsum[wid] = x;
    __syncthreads();
    if (wid == 0) {
        int w = wsum[lane];
#pragma unroll
        for (int d = 1; d < 32; d <<= 1) {
            int n = __shfl_up_sync(0xffffffffu, w, d);
            if (lane >= d) w += n;
        }
        wsum[lane] = w;
    }
    __syncthreads();
    int excl = (wid == 0 ? 0 : wsum[wid - 1]) + (x - tsum);

    if (excl < K && excl + tsum >= K) {     // exactly one thread
        int c = excl;
        for (int q = 0; q < per; q++) {
            int bin = base - q;
            int h = (int)hist[bin];
            if (c + h >= K) { *s_bin = bin; *s_above = c; break; }
            c += h;
        }
    }
    __syncthreads();
}

__global__ __launch_bounds__(1024) void topk_kernel(float* __restrict__ dout) {
    __shared__ unsigned int       hist[NBINS];    // 8 KB: coarse hist / refine hist
    __shared__ unsigned int       hc[NBINS];      // 8 KB: candidate count per bin
    __shared__ unsigned int       cbase[NBINS];   // 8 KB: suffix-scan group base
    __shared__ unsigned int       cur[NBINS];     // 8 KB: placement cursor per bin
    __shared__ unsigned long long cand[NCAND];    // 16 KB: bin-grouped candidates
    __shared__ int  wsum[32];
    __shared__ int  s_bin, s_above;
    __shared__ unsigned int s_total;

    int b = blockIdx.x;
    int tid = threadIdx.x;
    const uint4* sv = (const uint4*)(g_scores + b * NA);

    // Register-cache this thread's 9 uint4 chunks (single L2 read pass).
    uint4 vloc[NIT];
#pragma unroll
    for (int it = 0; it < NIT; it++) {
        int q = it * 1024 + tid;
        vloc[it] = (q < NA4) ? sv[q] : make_uint4(0u, 0u, 0u, 0u);
    }

    // Phase 1: coarse histogram on bits >> 19.
    for (int q = tid; q < NBINS; q += 1024) { hist[q] = 0u; hc[q] = 0u; cur[q] = 0u; }
    __syncthreads();
#pragma unroll
    for (int it = 0; it < NIT; it++) {
        uint4 v = vloc[it];
        atomicAdd(&hist[v.x >> 19], 1u);
        atomicAdd(&hist[v.y >> 19], 1u);
        atomicAdd(&hist[v.z >> 19], 1u);
        atomicAdd(&hist[v.w >> 19], 1u);
    }
    __syncthreads();
    find_thresh(hist, NBINS, K_TOP, tid, wsum, &s_bin, &s_above);
    int T = s_bin;
    int need2 = K_TOP - s_above;
    int binT_count = (int)hist[T];
    __syncthreads();

    unsigned int cut;
    if (s_above + binT_count <= NCAND) {
        cut = (unsigned int)T << 19;            // common case: candidates fit buffer
    } else {
        // Rare: refine bin T on bits[18:8] to bound candidate count.
        for (int q = tid; q < NSUB; q += 1024) hist[q] = 0u;
        __syncthreads();
#pragma unroll
        for (int it = 0; it < NIT; it++) {
            uint4 v = vloc[it];
            if ((int)(v.x >> 19) == T) atomicAdd(&hist[(v.x >> 8) & 2047u], 1u);
            if ((int)(v.y >> 19) == T) atomicAdd(&hist[(v.y >> 8) & 2047u], 1u);
            if ((int)(v.z >> 19) == T) atomicAdd(&hist[(v.z >> 8) & 2047u], 1u);
            if ((int)(v.w >> 19) == T) atomicAdd(&hist[(v.w >> 8) & 2047u], 1u);
        }
        __syncthreads();
        find_thresh(hist, NSUB, need2, tid, wsum, &s_bin, &s_above);
        cut = ((unsigned int)T << 19) | ((unsigned int)s_bin << 8);
        __syncthreads();
    }

    // Phase 2: count candidates (bits >= cut) per coarse bin.
#pragma unroll
    for (int it = 0; it < NIT; it++) {
        uint4 v = vloc[it];
        if (v.x >= cut) atomicAdd(&hc[v.x >> 19], 1u);
        if (v.y >= cut) atomicAdd(&hc[v.y >> 19], 1u);
        if (v.z >= cut) atomicAdd(&hc[v.z >> 19], 1u);
        if (v.w >= cut) atomicAdd(&hc[v.w >> 19], 1u);
    }
    __syncthreads();

    // Phase 3: descending suffix scan of hc -> cbase[bin] = #cands in bins > bin.
    // Thread tid owns bin pair (hi, hi-1) with hi = NBINS-1-2*tid.
    {
        int hi = NBINS - 1 - 2 * tid;
        unsigned int h1 = hc[hi], h0 = hc[hi - 1];
        int tsum = (int)(h1 + h0);
        int lane = tid & 31, wid = tid >> 5;
        int x = tsum;
#pragma unroll
        for (int d = 1; d < 32; d <<= 1) {
            int n = __shfl_up_sync(0xffffffffu, x, d);
            if (lane >= d) x += n;
        }
        if (lane == 31) wsum[wid] = x;
        __syncthreads();
        if (wid == 0) {
            int w = wsum[lane];
#pragma unroll
            for (int d = 1; d < 32; d <<= 1) {
                int n = __shfl_up_sync(0xffffffffu, w, d);
                if (lane >= d) w += n;
            }
            wsum[lane] = w;
        }
        __syncthreads();
        int excl = (wid == 0 ? 0 : wsum[wid - 1]) + (x - tsum);
        cbase[hi]     = (unsigned int)excl;
        cbase[hi - 1] = (unsigned int)excl + h1;
        if (hi - 1 == 0)                      // tid 1023 owns bins (1,0)
            s_total = (unsigned int)excl + h1 + h0;   // grand total candidates
    }
    __syncthreads();

    // Phase 4: place candidates grouped by bin: slot = cbase[bin] + cur[bin]++.
    // key = (bits << 32) | ~index : bigger key == better (score desc, idx asc).
#pragma unroll
    for (int it = 0; it < NIT; it++) {
        uint4 v = vloc[it];
        int a0 = (it * 1024 + tid) * 4;
#pragma unroll
        for (int e = 0; e < 4; e++) {
            unsigned int bits = (e == 0) ? v.x : (e == 1) ? v.y : (e == 2) ? v.z : v.w;
            if (bits >= cut) {
                unsigned int bin = bits >> 19;
                unsigned int slot = cbase[bin] + atomicAdd(&cur[bin], 1u);
                if (slot < NCAND)
                    cand[slot] = ((unsigned long long)bits << 32) |
                                 (unsigned long long)(0xFFFFFFFFu - (unsigned int)(a0 + e));
            }
        }
    }
    __syncthreads();
    int cnt = (int)s_total; if (cnt > NCAND) cnt = NCAND;
    // Every slot < cnt is a written, valid candidate (groups pack from slot 0).

    // Phase 5: exact rank = cbase[bin] + #same-bin candidates with larger key.
    // Valid keys have bits < 2^30 -> bin = key>>51 < 2048 (in-bounds).
#pragma unroll
    for (int s0 = 0; s0 < 2; s0++) {
        int s = tid + s0 * 1024;
        if (s < cnt) {
            unsigned long long key = cand[s];
            unsigned int bin   = (unsigned int)(key >> 51);
            unsigned int start = cbase[bin];
            unsigned int end   = start + hc[bin];
            if (end > (unsigned int)cnt) end = (unsigned int)cnt;
            int r = (int)start;
            for (unsigned int g = start; g < end; g++)
                r += (cand[g] > key);
            if (r < K_TOP) {
                unsigned int bits = (unsigned int)(key >> 32);
                unsigned int a    = 0xFFFFFFFFu - (unsigned int)(key & 0xFFFFFFFFull);
                g_keep[b * K_TOP + r] = (int)a;
                dout[b * (K_TOP * 5) + r * 5 + 4] = __uint_as_float(bits);
            }
        }
    }
}

// ---------------------------------------------------------------------------
// Kernel 3: decode kept anchors. Channel-major tasking (det fast index).
// (R4 version)
// ---------------------------------------------------------------------------
__global__ void decode_kernel(const float* __restrict__ bbox0, const float* __restrict__ bbox1,
                              const float* __restrict__ bbox2,
                              const float* __restrict__ kpt0,  const float* __restrict__ kpt1,
                              const float* __restrict__ kpt2,
                              const float* __restrict__ vis0,  const float* __restrict__ vis1,
                              const float* __restrict__ vis2,
                              float* __restrict__ dout) {
    const int NTASK = NDET * 18;
    int task = blockIdx.x * blockDim.x + threadIdx.x;
    if (task >= NTASK) return;
    int det = task % NDET;
    int sub = task / NDET;
    int b   = det / K_TOP;
    int a   = g_keep[det];

    int p, HW, l;
    float s, px, py;
    if (a < 25600)      { p = a;         HW = 25600; s = 8.0f;  l = 0; px = (float)(p % 160) * 8.0f;  py = (float)(p / 160) * 8.0f;  }
    else if (a < 32000) { p = a - 25600; HW = 6400;  s = 16.0f; l = 1; px = (float)(p % 80)  * 16.0f; py = (float)(p / 80)  * 16.0f; }
    else                { p = a - 32000; HW = 1600;  s = 32.0f; l = 2; px = (float)(p % 40)  * 32.0f; py = (float)(p / 40)  * 32.0f; }

    if (sub < 17) {
        int k = sub;
        const float* kp = (l == 0) ? kpt0 : (l == 1) ? kpt1 : kpt2;
        const float* vp = (l == 0) ? vis0 : (l == 1) ? vis1 : vis2;
        float kx = kp[(b * 34 + 2 * k)     * HW + p];
        float ky = kp[(b * 34 + 2 * k + 1) * HW + p];
        float v  = vp[(b * 17 + k)         * HW + p];
        int off = NDET * 5 + det * 51 + k * 3;
        dout[off + 0] = kx * s + px;
        dout[off + 1] = ky * s + py;
        dout[off + 2] = sigref(v);
    } else {
        const float* bp = (l == 0) ? bbox0 : (l == 1) ? bbox1 : bbox2;
        float bx = bp[(b * 4 + 0) * HW + p];
        float by = bp[(b * 4 + 1) * HW + p];
        float bw = bp[(b * 4 + 2) * HW + p];
        float bh = bp[(b * 4 + 3) * HW + p];
        float x  = bx * s + px;
        float y  = by * s + py;
        float hw = expf(bw) * s * 0.5f;
        float hh = expf(bh) * s * 0.5f;
        int off = det * 5;
        dout[off + 0] = x - hw;
        dout[off + 1] = y - hh;
        dout[off + 2] = x + hw;
        dout[off + 3] = y + hh;
    }
}

// ---------------------------------------------------------------------------
extern "C" void kernel_launch(void* const* d_in, const int* in_sizes, int n_in,
                              void* d_out, int out_size) {
    const float* cls0  = (const float*)d_in[0];
    const float* cls1  = (const float*)d_in[1];
    const float* cls2  = (const float*)d_in[2];
    const float* bbox0 = (const float*)d_in[3];
    const float* bbox1 = (const float*)d_in[4];
    const float* bbox2 = (const float*)d_in[5];
    const float* obj0  = (const float*)d_in[6];
    const float* obj1  = (const float*)d_in[7];
    const float* obj2  = (const float*)d_in[8];
    const float* kpt0  = (const float*)d_in[9];
    const float* kpt1  = (const float*)d_in[10];
    const float* kpt2  = (const float*)d_in[11];
    const float* vis0  = (const float*)d_in[12];
    const float* vis1  = (const float*)d_in[13];
    const float* vis2  = (const float*)d_in[14];
    float* dout = (float*)d_out;

    score_kernel<<<(NB * NA4 + 255) / 256, 256>>>(cls0, cls1, cls2, obj0, obj1, obj2);
    topk_kernel<<<NB, 1024>>>(dout);
    decode_kernel<<<(NDET * 18 + 255) / 256, 256>>>(bbox0, bbox1, bbox2,
                                                    kpt0, kpt1, kpt2,
                                                    vis0, vis1, vis2, dout);
}